// round 3
// baseline (speedup 1.0000x reference)
#include <cuda_runtime.h>
#include <cstdint>

#define B_   256
#define T_   128
#define IN_  128
#define H_   256
#define H3_  768
#define OUT_ 128

#define ROWS 8        // rows of (c,b) state per persistent block
#define NBLK 96       // 768 / ROWS
#define PTH  192      // threads per persistent block (each owns 4 consecutive cols)
#define KC   16       // k-chunk rows of Wh per bulk copy
#define NCHUNK (H_/KC)             // 16
#define CHUNK_BYTES (KC*H3_*4)     // 49152
#define SMEM_FLOATS (2048 + 6144 + 2*KC*H3_)   // hst + ghs + double-buffered Wh chunk
#define SMEM_BYTES  (SMEM_FLOATS*4 + 16)

// scratch (device globals: allocation-free)
__device__ float g_gx[(size_t)T_ * B_ * H3_];   // [t][b][3H] precomputed x@Wx+bx
__device__ float g_hT[3 * B_ * H_];             // final hidden state

// ---------------------------------------------------------------- helpers
static __device__ __forceinline__ uint32_t s2u(const void* p) {
    uint32_t a;
    asm("{ .reg .u64 t; cvta.to.shared.u64 t, %1; cvt.u32.u64 %0, t; }"
        : "=r"(a) : "l"(p));
    return a;
}
static __device__ __forceinline__ void mbar_init(uint32_t m, int cnt) {
    asm volatile("mbarrier.init.shared.b64 [%0], %1;" :: "r"(m), "r"(cnt) : "memory");
}
static __device__ __forceinline__ void mbar_expect(uint32_t m, uint32_t bytes) {
    asm volatile("mbarrier.arrive.expect_tx.shared.b64 _, [%0], %1;"
                 :: "r"(m), "r"(bytes) : "memory");
}
static __device__ __forceinline__ void mbar_wait(uint32_t m, int ph) {
    asm volatile(
        "{\n\t"
        ".reg .pred P;\n\t"
        "WL%=:\n\t"
        "mbarrier.try_wait.parity.acquire.cta.shared::cta.b64 P, [%0], %1;\n\t"
        "@P bra WD%=;\n\t"
        "bra WL%=;\n\t"
        "WD%=:\n\t"
        "}"
        :: "r"(m), "r"(ph) : "memory");
}
static __device__ __forceinline__ void bulk_g2s(uint32_t dst, const void* src,
                                                uint32_t bytes, uint32_t m) {
    asm volatile(
        "cp.async.bulk.shared::cluster.global.mbarrier::complete_tx::bytes [%0], [%1], %2, [%3];"
        :: "r"(dst), "l"(src), "r"(bytes), "r"(m) : "memory");
}
static __device__ __forceinline__ void fence_async() {
    asm volatile("fence.proxy.async.shared::cta;" ::: "memory");
}
static __device__ __forceinline__ float sigmoidf_(float x) {
    return 1.0f / (1.0f + __expf(-x));
}
static __device__ __forceinline__ float tanhf_(float x) {
    float ax = fabsf(x);
    float t  = __expf(-2.0f * ax);
    float r  = (1.0f - t) / (1.0f + t);
    return x >= 0.0f ? r : -r;
}

// ---------------------------------------------------------------- gx = x @ Wx + bx
// M = T*B = 32768 rows (m = t*256 + b), N = 768, K = 128. 64x64 tile, 4x4 micro.
__global__ void __launch_bounds__(256) k_gx(const float* __restrict__ x,
                                            const float* __restrict__ Wx,
                                            const float* __restrict__ bx) {
    __shared__ float As[16][65];
    __shared__ float Bs[16][64];
    const int tid = threadIdx.x;
    const int tx = tid & 15, ty = tid >> 4;
    const int n0 = blockIdx.x * 64;
    const int m0 = blockIdx.y * 64;

    float acc[4][4] = {};
    for (int k0 = 0; k0 < IN_; k0 += 16) {
#pragma unroll
        for (int i = 0; i < 4; i++) {
            int e  = tid + i * 256;
            int mm = e >> 4, kk = e & 15;
            int m  = m0 + mm;
            int tt = m >> 8, bb = m & 255;
            As[kk][mm] = x[bb * (T_ * IN_) + tt * IN_ + k0 + kk];
        }
#pragma unroll
        for (int i = 0; i < 4; i++) {
            int e  = tid + i * 256;
            int kk = e >> 6, nn = e & 63;
            Bs[kk][nn] = Wx[(k0 + kk) * H3_ + n0 + nn];
        }
        __syncthreads();
#pragma unroll
        for (int kk = 0; kk < 16; kk++) {
            float a[4];
#pragma unroll
            for (int i = 0; i < 4; i++) a[i] = As[kk][ty * 4 + i];
            float4 b4 = *(const float4*)&Bs[kk][tx * 4];
            float b[4] = { b4.x, b4.y, b4.z, b4.w };
#pragma unroll
            for (int i = 0; i < 4; i++)
#pragma unroll
                for (int j = 0; j < 4; j++) acc[i][j] = fmaf(a[i], b[j], acc[i][j]);
        }
        __syncthreads();
    }
    float4 bxv = *(const float4*)&bx[n0 + tx * 4];
#pragma unroll
    for (int i = 0; i < 4; i++) {
        float4 o;
        o.x = acc[i][0] + bxv.x;
        o.y = acc[i][1] + bxv.y;
        o.z = acc[i][2] + bxv.z;
        o.w = acc[i][3] + bxv.w;
        *(float4*)&g_gx[(size_t)(m0 + ty * 4 + i) * H3_ + n0 + tx * 4] = o;
    }
}

// ---------------------------------------------------------------- persistent CRU recurrence
// Block owns 8 consecutive (c,b) rows; h state lives in SMEM for all T steps.
// Per step: gh = h @ Wh (Wh streamed from L2 via cp.async.bulk, 2-deep pipeline),
// then fused GRU gate epilogue using precomputed gx.
__global__ void __launch_bounds__(PTH) k_cru(const float* __restrict__ h0,
                                             const float* __restrict__ Wh,
                                             const float* __restrict__ bh) {
    extern __shared__ float sm[];
    float* hst = sm;                      // [256][8]   h transposed: hst[k*8 + r]
    float* ghs = sm + 2048;               // [8][768]   per-step gh
    float* Bs  = sm + 2048 + 6144;        // [2][16][768] Wh chunk double buffer
    uint64_t* mb = (uint64_t*)(sm + SMEM_FLOATS);

    const int tid    = threadIdx.x;
    const int r0     = blockIdx.x * ROWS;
    const int b_base = r0 & (B_ - 1);
    const uint32_t mb0 = s2u(mb), mb1 = s2u(mb + 1);
    const uint32_t bsu0 = s2u(Bs), bsu1 = s2u(Bs + KC * H3_);

    // load initial h (hid_state[0]): h0[(r0+r)*H + k] -> hst[k*8 + r]
    for (int idx = tid; idx < ROWS * H_; idx += PTH)
        hst[(idx & (H_ - 1)) * ROWS + (idx >> 8)] = h0[r0 * H_ + idx];

    float bhv[4];
    {
        float4 t4 = *(const float4*)&bh[tid * 4];
        bhv[0] = t4.x; bhv[1] = t4.y; bhv[2] = t4.z; bhv[3] = t4.w;
    }

    if (tid == 0) {
        mbar_init(mb0, 1);
        mbar_init(mb1, 1);
        fence_async();
    }
    __syncthreads();

    if (tid == 0) {
        mbar_expect(mb0, CHUNK_BYTES);
        bulk_g2s(bsu0, Wh, CHUNK_BYTES, mb0);
        mbar_expect(mb1, CHUNK_BYTES);
        bulk_g2s(bsu1, Wh + KC * H3_, CHUNK_BYTES, mb1);
    }

    int ph0 = 0, ph1 = 0;
    int cc = 0;
    const int CCMAX = NCHUNK * T_;

    for (int t = 0; t < T_; t++) {
        float acc[ROWS][4];
#pragma unroll
        for (int r = 0; r < ROWS; r++)
#pragma unroll
            for (int c = 0; c < 4; c++) acc[r][c] = bhv[c];

        for (int chunk = 0; chunk < NCHUNK; chunk++) {
            const int buf = cc & 1;
            if (buf == 0) { mbar_wait(mb0, ph0); ph0 ^= 1; }
            else          { mbar_wait(mb1, ph1); ph1 ^= 1; }

            const float* bp = Bs + buf * (KC * H3_);
            const float* hp = hst + chunk * (KC * ROWS);
#pragma unroll
            for (int kk = 0; kk < KC; kk++) {
                float4 a0 = *(const float4*)(hp + kk * ROWS);
                float4 a1 = *(const float4*)(hp + kk * ROWS + 4);
                float4 b4 = *(const float4*)(bp + kk * H3_ + tid * 4);
                float av[8] = { a0.x, a0.y, a0.z, a0.w, a1.x, a1.y, a1.z, a1.w };
                float bv[4] = { b4.x, b4.y, b4.z, b4.w };
#pragma unroll
                for (int r = 0; r < ROWS; r++)
#pragma unroll
                    for (int c = 0; c < 4; c++)
                        acc[r][c] = fmaf(av[r], bv[c], acc[r][c]);
            }
            __syncthreads();   // all consumers done with this buffer
            if (tid == 0 && cc + 2 < CCMAX) {
                const int nch = (chunk + 2) & (NCHUNK - 1);
                const uint32_t m = buf ? mb1 : mb0;
                mbar_expect(m, CHUNK_BYTES);
                bulk_g2s(buf ? bsu1 : bsu0, Wh + nch * (KC * H3_), CHUNK_BYTES, m);
            }
            cc++;
        }

        // stash gh to SMEM so gate math can gather (r,z,n) segments per (row,j)
#pragma unroll
        for (int r = 0; r < ROWS; r++) {
            float4 o = { acc[r][0], acc[r][1], acc[r][2], acc[r][3] };
            *(float4*)&ghs[r * H3_ + tid * 4] = o;
        }
        __syncthreads();

        const float* gx = g_gx + (size_t)t * (B_ * H3_);
        for (int idx = tid; idx < ROWS * H_; idx += PTH) {
            const int r = idx >> 8, j = idx & 255;
            const float* gxp = gx + (size_t)(b_base + r) * H3_ + j;
            const float xr = gxp[0], xz = gxp[256], xn = gxp[512];
            const float hr = ghs[r * H3_ + j];
            const float hz = ghs[r * H3_ + 256 + j];
            const float hn = ghs[r * H3_ + 512 + j];
            const float rg = sigmoidf_(xr + hr);
            const float zg = sigmoidf_(xz + hz);
            const float ng = tanhf_(xn + rg * hn);
            const float ho = hst[j * ROWS + r];
            hst[j * ROWS + r] = ng + zg * (ho - ng);
        }
        __syncthreads();
    }

    for (int idx = tid; idx < ROWS * H_; idx += PTH)
        g_hT[r0 * H_ + idx] = hst[(idx & 255) * ROWS + (idx >> 8)];
}

// ---------------------------------------------------------------- out = elu((sum_c hT) @ Wf + bf)
__global__ void __launch_bounds__(128) k_out(const float* __restrict__ Wf,
                                             const float* __restrict__ bf,
                                             float* __restrict__ out) {
    __shared__ float s[H_];
    const int b = blockIdx.x;
    const int tid = threadIdx.x;
    for (int k = tid; k < H_; k += 128)
        s[k] = g_hT[b * H_ + k] + g_hT[B_ * H_ + b * H_ + k] + g_hT[2 * B_ * H_ + b * H_ + k];
    __syncthreads();
    float acc = bf[tid];
#pragma unroll 8
    for (int k = 0; k < H_; k++)
        acc = fmaf(s[k], Wf[k * OUT_ + tid], acc);
    out[b * OUT_ + tid] = acc > 0.0f ? acc : expm1f(acc);
}

// ---------------------------------------------------------------- feature = mean_b hT  -> (3, H)
__global__ void __launch_bounds__(128) k_feat(float* __restrict__ feat) {
    const int idx = blockIdx.x * 128 + threadIdx.x;   // 0..767
    const int c = idx >> 8, j = idx & 255;
    float s = 0.0f;
#pragma unroll 4
    for (int b = 0; b < B_; b++)
        s += g_hT[c * (B_ * H_) + b * H_ + j];
    feat[idx] = s * (1.0f / 256.0f);
}

// ---------------------------------------------------------------- launch
extern "C" void kernel_launch(void* const* d_in, const int* in_sizes, int n_in,
                              void* d_out, int out_size) {
    const float* x  = (const float*)d_in[0];
    const float* h0 = (const float*)d_in[1];
    const float* Wx = (const float*)d_in[2];
    const float* bx = (const float*)d_in[3];
    const float* Wh = (const float*)d_in[4];
    const float* bh = (const float*)d_in[5];
    const float* Wf = (const float*)d_in[6];
    const float* bf = (const float*)d_in[7];
    float* out = (float*)d_out;

    cudaFuncSetAttribute(k_cru, cudaFuncAttributeMaxDynamicSharedMemorySize, SMEM_BYTES);

    dim3 g1(H3_ / 64, (T_ * B_) / 64);   // (12, 512)
    k_gx<<<g1, 256>>>(x, Wx, bx);
    k_cru<<<NBLK, PTH, SMEM_BYTES>>>(h0, Wh, bh);
    k_out<<<B_, 128>>>(Wf, bf, out);
    k_feat<<<6, 128>>>(out + (out_size - 3 * H_));
}

// round 4
// speedup vs baseline: 1.5783x; 1.5783x over previous
#include <cuda_runtime.h>
#include <cstdint>

#define B_   256
#define T_   128
#define IN_  128
#define H_   256
#define H3_  768
#define OUT_ 128

#define ROWS 8        // (c,b) rows of state per persistent block
#define NBLK 96       // 768 / ROWS
#define PTH  256      // 8 warps: 2 per SMSP (balanced); thread j owns cols {j, j+256, j+512}
#define KC   32       // k-chunk rows of Wh per bulk copy
#define NCHUNK (H_/KC)             // 8
#define CHUNK_BYTES (KC*H3_*4)     // 98304
#define GX_BYTES (ROWS*H3_*4)      // 24576
#define HSTR 10                    // hst column stride (pad for bank spread + b64 align)
#define HST_FLOATS (H_*HSTR)       // 2560
#define BS_FLOATS  (2*KC*H3_)      // 49152
#define GXS_FLOATS (ROWS*H3_)      // 6144
#define SMEM_FLOATS (HST_FLOATS + BS_FLOATS + GXS_FLOATS)
#define SMEM_BYTES  (SMEM_FLOATS*4 + 32)   // + 3 mbarriers

// scratch (device globals: allocation-free)
__device__ float g_gx[(size_t)T_ * B_ * H3_];   // [t][b][3H] precomputed x@Wx+bx
__device__ float g_hT[3 * B_ * H_];             // final hidden state

// ---------------------------------------------------------------- helpers
static __device__ __forceinline__ uint32_t s2u(const void* p) {
    uint32_t a;
    asm("{ .reg .u64 t; cvta.to.shared.u64 t, %1; cvt.u32.u64 %0, t; }"
        : "=r"(a) : "l"(p));
    return a;
}
static __device__ __forceinline__ void mbar_init(uint32_t m, int cnt) {
    asm volatile("mbarrier.init.shared.b64 [%0], %1;" :: "r"(m), "r"(cnt) : "memory");
}
static __device__ __forceinline__ void mbar_expect(uint32_t m, uint32_t bytes) {
    asm volatile("mbarrier.arrive.expect_tx.shared.b64 _, [%0], %1;"
                 :: "r"(m), "r"(bytes) : "memory");
}
static __device__ __forceinline__ void mbar_wait(uint32_t m, int ph) {
    asm volatile(
        "{\n\t"
        ".reg .pred P;\n\t"
        "WL%=:\n\t"
        "mbarrier.try_wait.parity.acquire.cta.shared::cta.b64 P, [%0], %1;\n\t"
        "@P bra WD%=;\n\t"
        "bra WL%=;\n\t"
        "WD%=:\n\t"
        "}"
        :: "r"(m), "r"(ph) : "memory");
}
static __device__ __forceinline__ void bulk_g2s(uint32_t dst, const void* src,
                                                uint32_t bytes, uint32_t m) {
    asm volatile(
        "cp.async.bulk.shared::cluster.global.mbarrier::complete_tx::bytes [%0], [%1], %2, [%3];"
        :: "r"(dst), "l"(src), "r"(bytes), "r"(m) : "memory");
}
static __device__ __forceinline__ void fence_async() {
    asm volatile("fence.proxy.async.shared::cta;" ::: "memory");
}
// packed fp32x2 ops
static __device__ __forceinline__ uint64_t pack2(float v) {
    uint64_t r;
    asm("mov.b64 %0, {%1, %1};" : "=l"(r) : "f"(v));
    return r;
}
static __device__ __forceinline__ void fma2(uint64_t& d, uint64_t a, uint64_t b) {
    asm("fma.rn.f32x2 %0, %1, %2, %0;" : "+l"(d) : "l"(a), "l"(b));
}
static __device__ __forceinline__ float f32x2_lo(uint64_t v) {
    return __uint_as_float((uint32_t)v);
}
static __device__ __forceinline__ float f32x2_hi(uint64_t v) {
    return __uint_as_float((uint32_t)(v >> 32));
}
static __device__ __forceinline__ float sigmoidf_(float x) {
    return __fdividef(1.0f, 1.0f + __expf(-x));
}
static __device__ __forceinline__ float tanhf_(float x) {
    float ax = fabsf(x);
    float t  = __expf(-2.0f * ax);
    float r  = __fdividef(1.0f - t, 1.0f + t);
    return x >= 0.0f ? r : -r;
}

// ---------------------------------------------------------------- gx = x @ Wx + bx  (FFMA2)
// M = T*B = 32768 rows (m = t*256 + b), N = 768, K = 128. 64x64 tile, 4x4 micro, row-pair packed.
__global__ void __launch_bounds__(256) k_gx(const float* __restrict__ x,
                                            const float* __restrict__ Wx,
                                            const float* __restrict__ bx) {
    __shared__ float As[16 * 66];   // stride 66: 8B-aligned row pairs, conflict-free stores
    __shared__ float Bs[16 * 64];
    const int tid = threadIdx.x;
    const int tx = tid & 15, ty = tid >> 4;
    const int n0 = blockIdx.x * 64;
    const int m0 = blockIdx.y * 64;

    uint64_t acc2[2][4];
#pragma unroll
    for (int p = 0; p < 2; p++)
#pragma unroll
        for (int c = 0; c < 4; c++) acc2[p][c] = 0ULL;

    for (int k0 = 0; k0 < IN_; k0 += 16) {
#pragma unroll
        for (int i = 0; i < 4; i++) {
            int e  = tid + i * 256;
            int mm = e >> 4, kk = e & 15;
            int m  = m0 + mm;
            int tt = m >> 8, bb = m & 255;
            As[kk * 66 + mm] = x[bb * (T_ * IN_) + tt * IN_ + k0 + kk];
        }
#pragma unroll
        for (int i = 0; i < 4; i++) {
            int e  = tid + i * 256;
            int kk = e >> 6, nn = e & 63;
            Bs[kk * 64 + nn] = Wx[(k0 + kk) * H3_ + n0 + nn];
        }
        __syncthreads();
#pragma unroll
        for (int kk = 0; kk < 16; kk++) {
            uint64_t a01 = *(const uint64_t*)&As[kk * 66 + ty * 4];
            uint64_t a23 = *(const uint64_t*)&As[kk * 66 + ty * 4 + 2];
            float4 b4 = *(const float4*)&Bs[kk * 64 + tx * 4];
            uint64_t p0 = pack2(b4.x), p1 = pack2(b4.y);
            uint64_t p2 = pack2(b4.z), p3 = pack2(b4.w);
            fma2(acc2[0][0], a01, p0); fma2(acc2[0][1], a01, p1);
            fma2(acc2[0][2], a01, p2); fma2(acc2[0][3], a01, p3);
            fma2(acc2[1][0], a23, p0); fma2(acc2[1][1], a23, p1);
            fma2(acc2[1][2], a23, p2); fma2(acc2[1][3], a23, p3);
        }
        __syncthreads();
    }
    float4 bxv = *(const float4*)&bx[n0 + tx * 4];
#pragma unroll
    for (int p = 0; p < 2; p++) {
        float4 lo4, hi4;
        lo4.x = f32x2_lo(acc2[p][0]) + bxv.x;  hi4.x = f32x2_hi(acc2[p][0]) + bxv.x;
        lo4.y = f32x2_lo(acc2[p][1]) + bxv.y;  hi4.y = f32x2_hi(acc2[p][1]) + bxv.y;
        lo4.z = f32x2_lo(acc2[p][2]) + bxv.z;  hi4.z = f32x2_hi(acc2[p][2]) + bxv.z;
        lo4.w = f32x2_lo(acc2[p][3]) + bxv.w;  hi4.w = f32x2_hi(acc2[p][3]) + bxv.w;
        *(float4*)&g_gx[(size_t)(m0 + ty * 4 + 2 * p)     * H3_ + n0 + tx * 4] = lo4;
        *(float4*)&g_gx[(size_t)(m0 + ty * 4 + 2 * p + 1) * H3_ + n0 + tx * 4] = hi4;
    }
}

// ---------------------------------------------------------------- persistent CRU recurrence
// Block owns 8 consecutive (c,b) rows; h state lives in SMEM (transposed, row-pair packed).
// Thread j owns gate-triplet columns {j, j+256, j+512} -> gates computed fully in registers.
// Per step: gh = h @ Wh via fma.rn.f32x2 (Wh streamed from L2 via cp.async.bulk, 2-deep),
// gx tile for the step prefetched into SMEM via TMA under the GEMM.
__global__ void __launch_bounds__(PTH) k_cru(const float* __restrict__ h0,
                                             const float* __restrict__ Wh,
                                             const float* __restrict__ bh) {
    extern __shared__ float sm[];
    float* hst = sm;                               // [256][HSTR] h transposed (pairs packed)
    float* Bs  = sm + HST_FLOATS;                  // [2][32][768] Wh chunk double buffer
    float* gxs = sm + HST_FLOATS + BS_FLOATS;      // [8][768] gx tile for current step
    uint64_t* mb = (uint64_t*)(sm + SMEM_FLOATS);

    const int tid    = threadIdx.x;                // = column j (0..255)
    const int r0     = blockIdx.x * ROWS;
    const int b_base = r0 & (B_ - 1);
    const uint32_t mb0 = s2u(mb), mb1 = s2u(mb + 1), mb2 = s2u(mb + 2);
    const uint32_t bsu0 = s2u(Bs), bsu1 = s2u(Bs + KC * H3_);
    const uint32_t gxsu = s2u(gxs);

    // load initial h: h0[(r0+r)*H + k] -> hst[k*HSTR + r]
    for (int idx = tid; idx < ROWS * H_; idx += PTH)
        hst[(idx & (H_ - 1)) * HSTR + (idx >> 8)] = h0[r0 * H_ + idx];

    uint64_t bh2[3];
#pragma unroll
    for (int g = 0; g < 3; g++) bh2[g] = pack2(bh[g * H_ + tid]);

    if (tid == 0) {
        mbar_init(mb0, 1);
        mbar_init(mb1, 1);
        mbar_init(mb2, 1);
        fence_async();
    }
    __syncthreads();

    if (tid == 0) {
        mbar_expect(mb0, CHUNK_BYTES);
        bulk_g2s(bsu0, Wh, CHUNK_BYTES, mb0);
        mbar_expect(mb1, CHUNK_BYTES);
        bulk_g2s(bsu1, Wh + KC * H3_, CHUNK_BYTES, mb1);
    }

    int ph0 = 0, ph1 = 0, ph2 = 0;
    int cc = 0;
    const int CCMAX = NCHUNK * T_;

    for (int t = 0; t < T_; t++) {
        // prefetch this step's gx tile (consumed in the epilogue, hidden under GEMM)
        if (tid == 0) {
            mbar_expect(mb2, GX_BYTES);
            bulk_g2s(gxsu, g_gx + (size_t)t * (B_ * H3_) + (size_t)b_base * H3_,
                     GX_BYTES, mb2);
        }

        uint64_t acc[4][3];
#pragma unroll
        for (int rp = 0; rp < 4; rp++)
#pragma unroll
            for (int g = 0; g < 3; g++) acc[rp][g] = bh2[g];

        for (int chunk = 0; chunk < NCHUNK; chunk++) {
            const int buf = cc & 1;
            if (buf == 0) { mbar_wait(mb0, ph0); ph0 ^= 1; }
            else          { mbar_wait(mb1, ph1); ph1 ^= 1; }

            const float* bp = Bs + buf * (KC * H3_);
            const float* hp = hst + chunk * (KC * HSTR);
#pragma unroll
            for (int kk = 0; kk < KC; kk++) {
                uint64_t a01 = *(const uint64_t*)(hp + kk * HSTR + 0);
                uint64_t a23 = *(const uint64_t*)(hp + kk * HSTR + 2);
                uint64_t a45 = *(const uint64_t*)(hp + kk * HSTR + 4);
                uint64_t a67 = *(const uint64_t*)(hp + kk * HSTR + 6);
                uint64_t p0 = pack2(bp[kk * H3_ + tid]);
                uint64_t p1 = pack2(bp[kk * H3_ + H_ + tid]);
                uint64_t p2 = pack2(bp[kk * H3_ + 2 * H_ + tid]);
                fma2(acc[0][0], a01, p0); fma2(acc[0][1], a01, p1); fma2(acc[0][2], a01, p2);
                fma2(acc[1][0], a23, p0); fma2(acc[1][1], a23, p1); fma2(acc[1][2], a23, p2);
                fma2(acc[2][0], a45, p0); fma2(acc[2][1], a45, p1); fma2(acc[2][2], a45, p2);
                fma2(acc[3][0], a67, p0); fma2(acc[3][1], a67, p1); fma2(acc[3][2], a67, p2);
            }
            __syncthreads();   // all consumers done with this buffer
            if (tid == 0 && cc + 2 < CCMAX) {
                const int nch = (chunk + 2) & (NCHUNK - 1);
                const uint32_t m = buf ? mb1 : mb0;
                mbar_expect(m, CHUNK_BYTES);
                bulk_g2s(buf ? bsu1 : bsu0, Wh + nch * (KC * H3_), CHUNK_BYTES, m);
            }
            cc++;
        }

        // gate epilogue — fully register-resident per column j
        mbar_wait(mb2, ph2); ph2 ^= 1;
#pragma unroll
        for (int r = 0; r < ROWS; r++) {
            const int rp = r >> 1;
            const bool hi = r & 1;
            const float hr = hi ? f32x2_hi(acc[rp][0]) : f32x2_lo(acc[rp][0]);
            const float hz = hi ? f32x2_hi(acc[rp][1]) : f32x2_lo(acc[rp][1]);
            const float hn = hi ? f32x2_hi(acc[rp][2]) : f32x2_lo(acc[rp][2]);
            const float xr = gxs[r * H3_ + tid];
            const float xz = gxs[r * H3_ + H_ + tid];
            const float xn = gxs[r * H3_ + 2 * H_ + tid];
            const float rg = sigmoidf_(xr + hr);
            const float zg = sigmoidf_(xz + hz);
            const float ng = tanhf_(xn + rg * hn);
            const float ho = hst[tid * HSTR + r];
            hst[tid * HSTR + r] = ng + zg * (ho - ng);
        }
        __syncthreads();
    }

    for (int idx = tid; idx < ROWS * H_; idx += PTH)
        g_hT[r0 * H_ + idx] = hst[(idx & (H_ - 1)) * HSTR + (idx >> 8)];
}

// ---------------------------------------------------------------- out = elu((sum_c hT) @ Wf + bf)
__global__ void __launch_bounds__(128) k_out(const float* __restrict__ Wf,
                                             const float* __restrict__ bf,
                                             float* __restrict__ out) {
    __shared__ float s[H_];
    const int b = blockIdx.x;
    const int tid = threadIdx.x;
    for (int k = tid; k < H_; k += 128)
        s[k] = g_hT[b * H_ + k] + g_hT[B_ * H_ + b * H_ + k] + g_hT[2 * B_ * H_ + b * H_ + k];
    __syncthreads();
    float acc = bf[tid];
#pragma unroll 8
    for (int k = 0; k < H_; k++)
        acc = fmaf(s[k], Wf[k * OUT_ + tid], acc);
    out[b * OUT_ + tid] = acc > 0.0f ? acc : expm1f(acc);
}

// ---------------------------------------------------------------- feature = mean_b hT -> (3, H)
// 24 blocks x 256 threads: warp-row ty sums a 32-batch slice, deterministic smem tree.
__global__ void __launch_bounds__(256) k_feat(float* __restrict__ feat) {
    __shared__ float p[8][32];
    const int tx = threadIdx.x & 31, ty = threadIdx.x >> 5;
    const int jg = blockIdx.x * 32 + tx;            // 0..767
    const int c = jg >> 8, j = jg & 255;
    float s = 0.0f;
#pragma unroll 8
    for (int i = 0; i < 32; i++) {
        const int b = ty * 32 + i;
        s += g_hT[c * (B_ * H_) + b * H_ + j];
    }
    p[ty][tx] = s;
    __syncthreads();
    if (ty == 0) {
        float acc = 0.0f;
#pragma unroll
        for (int q = 0; q < 8; q++) acc += p[q][tx];
        feat[jg] = acc * (1.0f / 256.0f);
    }
}

// ---------------------------------------------------------------- launch
extern "C" void kernel_launch(void* const* d_in, const int* in_sizes, int n_in,
                              void* d_out, int out_size) {
    const float* x  = (const float*)d_in[0];
    const float* h0 = (const float*)d_in[1];
    const float* Wx = (const float*)d_in[2];
    const float* bx = (const float*)d_in[3];
    const float* Wh = (const float*)d_in[4];
    const float* bh = (const float*)d_in[5];
    const float* Wf = (const float*)d_in[6];
    const float* bf = (const float*)d_in[7];
    float* out = (float*)d_out;

    cudaFuncSetAttribute(k_cru, cudaFuncAttributeMaxDynamicSharedMemorySize, SMEM_BYTES);

    dim3 g1(H3_ / 64, (T_ * B_) / 64);   // (12, 512)
    k_gx<<<g1, 256>>>(x, Wx, bx);
    k_cru<<<NBLK, PTH, SMEM_BYTES>>>(h0, Wh, bh);
    k_out<<<B_, 128>>>(Wf, bf, out);
    k_feat<<<24, 256>>>(out + (out_size - 3 * H_));
}

// round 5
// speedup vs baseline: 1.6672x; 1.0564x over previous
#include <cuda_runtime.h>
#include <cstdint>

#define B_   256
#define T_   128
#define IN_  128
#define H_   256
#define H3_  768
#define OUT_ 128

#define ROWS 8        // (c,b) rows of state per persistent block
#define NBLK 96       // 768 / ROWS
#define PTH  256      // 8 warps: 2 per SMSP (balanced); thread j owns cols {j, j+256, j+512}
#define KC   32       // k-chunk rows of Wh per bulk copy
#define NCHUNK (H_/KC)             // 8
#define CHUNK_BYTES (KC*H3_*4)     // 98304
#define GX_BYTES (ROWS*H3_*4)      // 24576
#define HSTR 10                    // hst column stride (pad for bank spread + b64 align)
#define HST_FLOATS (H_*HSTR)       // 2560
#define BS_FLOATS  (2*KC*H3_)      // 49152
#define GXS_FLOATS (ROWS*H3_)      // 6144
#define SMEM_FLOATS (HST_FLOATS + BS_FLOATS + GXS_FLOATS)
#define SMEM_BYTES  (SMEM_FLOATS*4 + 32)   // + 3 mbarriers

// scratch (device globals: allocation-free)
__device__ float g_gx[(size_t)T_ * B_ * H3_];   // [t][b][3H] precomputed x@Wx+bx
__device__ float g_hT[3 * B_ * H_];             // final hidden state

// ---------------------------------------------------------------- helpers
static __device__ __forceinline__ uint32_t s2u(const void* p) {
    uint32_t a;
    asm("{ .reg .u64 t; cvta.to.shared.u64 t, %1; cvt.u32.u64 %0, t; }"
        : "=r"(a) : "l"(p));
    return a;
}
static __device__ __forceinline__ void mbar_init(uint32_t m, int cnt) {
    asm volatile("mbarrier.init.shared.b64 [%0], %1;" :: "r"(m), "r"(cnt) : "memory");
}
static __device__ __forceinline__ void mbar_expect(uint32_t m, uint32_t bytes) {
    asm volatile("mbarrier.arrive.expect_tx.shared.b64 _, [%0], %1;"
                 :: "r"(m), "r"(bytes) : "memory");
}
static __device__ __forceinline__ void mbar_wait(uint32_t m, int ph) {
    asm volatile(
        "{\n\t"
        ".reg .pred P;\n\t"
        "WL%=:\n\t"
        "mbarrier.try_wait.parity.acquire.cta.shared::cta.b64 P, [%0], %1;\n\t"
        "@P bra WD%=;\n\t"
        "bra WL%=;\n\t"
        "WD%=:\n\t"
        "}"
        :: "r"(m), "r"(ph) : "memory");
}
static __device__ __forceinline__ void bulk_g2s(uint32_t dst, const void* src,
                                                uint32_t bytes, uint32_t m) {
    asm volatile(
        "cp.async.bulk.shared::cluster.global.mbarrier::complete_tx::bytes [%0], [%1], %2, [%3];"
        :: "r"(dst), "l"(src), "r"(bytes), "r"(m) : "memory");
}
static __device__ __forceinline__ void fence_async() {
    asm volatile("fence.proxy.async.shared::cta;" ::: "memory");
}
// packed fp32x2 ops
static __device__ __forceinline__ uint64_t pack2(float v) {
    uint64_t r;
    asm("mov.b64 %0, {%1, %1};" : "=l"(r) : "f"(v));
    return r;
}
static __device__ __forceinline__ void fma2(uint64_t& d, uint64_t a, uint64_t b) {
    asm("fma.rn.f32x2 %0, %1, %2, %0;" : "+l"(d) : "l"(a), "l"(b));
}
static __device__ __forceinline__ float f32x2_lo(uint64_t v) {
    return __uint_as_float((uint32_t)v);
}
static __device__ __forceinline__ float f32x2_hi(uint64_t v) {
    return __uint_as_float((uint32_t)(v >> 32));
}
static __device__ __forceinline__ float sigmoidf_(float x) {
    return __fdividef(1.0f, 1.0f + __expf(-x));
}
static __device__ __forceinline__ float tanhf_(float x) {
    float ax = fabsf(x);
    float t  = __expf(-2.0f * ax);
    float r  = __fdividef(1.0f - t, 1.0f + t);
    return x >= 0.0f ? r : -r;
}

// ---------------------------------------------------------------- gx = x @ Wx + bx  (FFMA2)
// M = T*B = 32768 rows (m = t*256 + b), N = 768, K = 128. 64x64 tile, 4x4 micro, row-pair packed.
__global__ void __launch_bounds__(256) k_gx(const float* __restrict__ x,
                                            const float* __restrict__ Wx,
                                            const float* __restrict__ bx) {
    __shared__ float As[16 * 66];   // stride 66: 8B-aligned row pairs, conflict-free stores
    __shared__ float Bs[16 * 64];
    const int tid = threadIdx.x;
    const int tx = tid & 15, ty = tid >> 4;
    const int n0 = blockIdx.x * 64;
    const int m0 = blockIdx.y * 64;

    uint64_t acc2[2][4];
#pragma unroll
    for (int p = 0; p < 2; p++)
#pragma unroll
        for (int c = 0; c < 4; c++) acc2[p][c] = 0ULL;

    for (int k0 = 0; k0 < IN_; k0 += 16) {
#pragma unroll
        for (int i = 0; i < 4; i++) {
            int e  = tid + i * 256;
            int mm = e >> 4, kk = e & 15;
            int m  = m0 + mm;
            int tt = m >> 8, bb = m & 255;
            As[kk * 66 + mm] = x[bb * (T_ * IN_) + tt * IN_ + k0 + kk];
        }
#pragma unroll
        for (int i = 0; i < 4; i++) {
            int e  = tid + i * 256;
            int kk = e >> 6, nn = e & 63;
            Bs[kk * 64 + nn] = Wx[(k0 + kk) * H3_ + n0 + nn];
        }
        __syncthreads();
#pragma unroll
        for (int kk = 0; kk < 16; kk++) {
            uint64_t a01 = *(const uint64_t*)&As[kk * 66 + ty * 4];
            uint64_t a23 = *(const uint64_t*)&As[kk * 66 + ty * 4 + 2];
            float4 b4 = *(const float4*)&Bs[kk * 64 + tx * 4];
            uint64_t p0 = pack2(b4.x), p1 = pack2(b4.y);
            uint64_t p2 = pack2(b4.z), p3 = pack2(b4.w);
            fma2(acc2[0][0], a01, p0); fma2(acc2[0][1], a01, p1);
            fma2(acc2[0][2], a01, p2); fma2(acc2[0][3], a01, p3);
            fma2(acc2[1][0], a23, p0); fma2(acc2[1][1], a23, p1);
            fma2(acc2[1][2], a23, p2); fma2(acc2[1][3], a23, p3);
        }
        __syncthreads();
    }
    float4 bxv = *(const float4*)&bx[n0 + tx * 4];
#pragma unroll
    for (int p = 0; p < 2; p++) {
        float4 lo4, hi4;
        lo4.x = f32x2_lo(acc2[p][0]) + bxv.x;  hi4.x = f32x2_hi(acc2[p][0]) + bxv.x;
        lo4.y = f32x2_lo(acc2[p][1]) + bxv.y;  hi4.y = f32x2_hi(acc2[p][1]) + bxv.y;
        lo4.z = f32x2_lo(acc2[p][2]) + bxv.z;  hi4.z = f32x2_hi(acc2[p][2]) + bxv.z;
        lo4.w = f32x2_lo(acc2[p][3]) + bxv.w;  hi4.w = f32x2_hi(acc2[p][3]) + bxv.w;
        *(float4*)&g_gx[(size_t)(m0 + ty * 4 + 2 * p)     * H3_ + n0 + tx * 4] = lo4;
        *(float4*)&g_gx[(size_t)(m0 + ty * 4 + 2 * p + 1) * H3_ + n0 + tx * 4] = hi4;
    }
}

// ---------------------------------------------------------------- persistent CRU recurrence
// Block owns 8 consecutive (c,b) rows; h state lives in SMEM (transposed, row-pair packed).
// Thread j owns gate-triplet columns {j, j+256, j+512} -> gates computed fully in registers.
// Per step: gh = h @ Wh via fma.rn.f32x2 (Wh streamed from L2 via cp.async.bulk, 2-deep),
// gx tile for the step prefetched into SMEM via TMA under the GEMM.
__global__ void __launch_bounds__(PTH) k_cru(const float* __restrict__ h0,
                                             const float* __restrict__ Wh,
                                             const float* __restrict__ bh) {
    extern __shared__ float sm[];
    float* hst = sm;                               // [256][HSTR] h transposed (pairs packed)
    float* Bs  = sm + HST_FLOATS;                  // [2][32][768] Wh chunk double buffer
    float* gxs = sm + HST_FLOATS + BS_FLOATS;      // [8][768] gx tile for current step
    uint64_t* mb = (uint64_t*)(sm + SMEM_FLOATS);

    const int tid    = threadIdx.x;                // = column j (0..255)
    const int r0     = blockIdx.x * ROWS;
    const int b_base = r0 & (B_ - 1);
    const uint32_t mb0 = s2u(mb), mb1 = s2u(mb + 1), mb2 = s2u(mb + 2);
    const uint32_t bsu0 = s2u(Bs), bsu1 = s2u(Bs + KC * H3_);
    const uint32_t gxsu = s2u(gxs);

    // load initial h: h0[(r0+r)*H + k] -> hst[k*HSTR + r]
    for (int idx = tid; idx < ROWS * H_; idx += PTH)
        hst[(idx & (H_ - 1)) * HSTR + (idx >> 8)] = h0[r0 * H_ + idx];

    uint64_t bh2[3];
#pragma unroll
    for (int g = 0; g < 3; g++) bh2[g] = pack2(bh[g * H_ + tid]);

    if (tid == 0) {
        mbar_init(mb0, 1);
        mbar_init(mb1, 1);
        mbar_init(mb2, 1);
        fence_async();
    }
    __syncthreads();

    if (tid == 0) {
        mbar_expect(mb0, CHUNK_BYTES);
        bulk_g2s(bsu0, Wh, CHUNK_BYTES, mb0);
        mbar_expect(mb1, CHUNK_BYTES);
        bulk_g2s(bsu1, Wh + KC * H3_, CHUNK_BYTES, mb1);
    }

    int ph0 = 0, ph1 = 0, ph2 = 0;
    int cc = 0;
    const int CCMAX = NCHUNK * T_;

    for (int t = 0; t < T_; t++) {
        // prefetch this step's gx tile (consumed in the epilogue, hidden under GEMM)
        if (tid == 0) {
            mbar_expect(mb2, GX_BYTES);
            bulk_g2s(gxsu, g_gx + (size_t)t * (B_ * H3_) + (size_t)b_base * H3_,
                     GX_BYTES, mb2);
        }

        uint64_t acc[4][3];
#pragma unroll
        for (int rp = 0; rp < 4; rp++)
#pragma unroll
            for (int g = 0; g < 3; g++) acc[rp][g] = bh2[g];

        for (int chunk = 0; chunk < NCHUNK; chunk++) {
            const int buf = cc & 1;
            if (buf == 0) { mbar_wait(mb0, ph0); ph0 ^= 1; }
            else          { mbar_wait(mb1, ph1); ph1 ^= 1; }

            const float* bp = Bs + buf * (KC * H3_);
            const float* hp = hst + chunk * (KC * HSTR);
#pragma unroll
            for (int kk = 0; kk < KC; kk++) {
                uint64_t a01 = *(const uint64_t*)(hp + kk * HSTR + 0);
                uint64_t a23 = *(const uint64_t*)(hp + kk * HSTR + 2);
                uint64_t a45 = *(const uint64_t*)(hp + kk * HSTR + 4);
                uint64_t a67 = *(const uint64_t*)(hp + kk * HSTR + 6);
                uint64_t p0 = pack2(bp[kk * H3_ + tid]);
                uint64_t p1 = pack2(bp[kk * H3_ + H_ + tid]);
                uint64_t p2 = pack2(bp[kk * H3_ + 2 * H_ + tid]);
                fma2(acc[0][0], a01, p0); fma2(acc[0][1], a01, p1); fma2(acc[0][2], a01, p2);
                fma2(acc[1][0], a23, p0); fma2(acc[1][1], a23, p1); fma2(acc[1][2], a23, p2);
                fma2(acc[2][0], a45, p0); fma2(acc[2][1], a45, p1); fma2(acc[2][2], a45, p2);
                fma2(acc[3][0], a67, p0); fma2(acc[3][1], a67, p1); fma2(acc[3][2], a67, p2);
            }
            __syncthreads();   // all consumers done with this buffer
            if (tid == 0 && cc + 2 < CCMAX) {
                const int nch = (chunk + 2) & (NCHUNK - 1);
                const uint32_t m = buf ? mb1 : mb0;
                mbar_expect(m, CHUNK_BYTES);
                bulk_g2s(buf ? bsu1 : bsu0, Wh + nch * (KC * H3_), CHUNK_BYTES, m);
            }
            cc++;
        }

        // gate epilogue — fully register-resident per column j
        mbar_wait(mb2, ph2); ph2 ^= 1;
#pragma unroll
        for (int r = 0; r < ROWS; r++) {
            const int rp = r >> 1;
            const bool hi = r & 1;
            const float hr = hi ? f32x2_hi(acc[rp][0]) : f32x2_lo(acc[rp][0]);
            const float hz = hi ? f32x2_hi(acc[rp][1]) : f32x2_lo(acc[rp][1]);
            const float hn = hi ? f32x2_hi(acc[rp][2]) : f32x2_lo(acc[rp][2]);
            const float xr = gxs[r * H3_ + tid];
            const float xz = gxs[r * H3_ + H_ + tid];
            const float xn = gxs[r * H3_ + 2 * H_ + tid];
            const float rg = sigmoidf_(xr + hr);
            const float zg = sigmoidf_(xz + hz);
            const float ng = tanhf_(xn + rg * hn);
            const float ho = hst[tid * HSTR + r];
            hst[tid * HSTR + r] = ng + zg * (ho - ng);
        }
        __syncthreads();
    }

    for (int idx = tid; idx < ROWS * H_; idx += PTH)
        g_hT[r0 * H_ + idx] = hst[(idx & (H_ - 1)) * HSTR + (idx >> 8)];
}

// ---------------------------------------------------------------- out = elu((sum_c hT) @ Wf + bf)
__global__ void __launch_bounds__(128) k_out(const float* __restrict__ Wf,
                                             const float* __restrict__ bf,
                                             float* __restrict__ out) {
    __shared__ float s[H_];
    const int b = blockIdx.x;
    const int tid = threadIdx.x;
    for (int k = tid; k < H_; k += 128)
        s[k] = g_hT[b * H_ + k] + g_hT[B_ * H_ + b * H_ + k] + g_hT[2 * B_ * H_ + b * H_ + k];
    __syncthreads();
    float acc = bf[tid];
#pragma unroll 8
    for (int k = 0; k < H_; k++)
        acc = fmaf(s[k], Wf[k * OUT_ + tid], acc);
    out[b * OUT_ + tid] = acc > 0.0f ? acc : expm1f(acc);
}

// ---------------------------------------------------------------- feature = mean_b hT -> (3, H)
// 24 blocks x 256 threads: warp-row ty sums a 32-batch slice, deterministic smem tree.
__global__ void __launch_bounds__(256) k_feat(float* __restrict__ feat) {
    __shared__ float p[8][32];
    const int tx = threadIdx.x & 31, ty = threadIdx.x >> 5;
    const int jg = blockIdx.x * 32 + tx;            // 0..767
    const int c = jg >> 8, j = jg & 255;
    float s = 0.0f;
#pragma unroll 8
    for (int i = 0; i < 32; i++) {
        const int b = ty * 32 + i;
        s += g_hT[c * (B_ * H_) + b * H_ + j];
    }
    p[ty][tx] = s;
    __syncthreads();
    if (ty == 0) {
        float acc = 0.0f;
#pragma unroll
        for (int q = 0; q < 8; q++) acc += p[q][tx];
        feat[jg] = acc * (1.0f / 256.0f);
    }
}

// ---------------------------------------------------------------- launch
extern "C" void kernel_launch(void* const* d_in, const int* in_sizes, int n_in,
                              void* d_out, int out_size) {
    const float* x  = (const float*)d_in[0];
    const float* h0 = (const float*)d_in[1];
    const float* Wx = (const float*)d_in[2];
    const float* bx = (const float*)d_in[3];
    const float* Wh = (const float*)d_in[4];
    const float* bh = (const float*)d_in[5];
    const float* Wf = (const float*)d_in[6];
    const float* bf = (const float*)d_in[7];
    float* out = (float*)d_out;

    cudaFuncSetAttribute(k_cru, cudaFuncAttributeMaxDynamicSharedMemorySize, SMEM_BYTES);

    dim3 g1(H3_ / 64, (T_ * B_) / 64);   // (12, 512)
    k_gx<<<g1, 256>>>(x, Wx, bx);
    k_cru<<<NBLK, PTH, SMEM_BYTES>>>(h0, Wh, bh);
    k_out<<<B_, 128>>>(Wf, bf, out);
    k_feat<<<24, 256>>>(out + (out_size - 3 * H_));
}